// round 4
// baseline (speedup 1.0000x reference)
#include <cuda_runtime.h>
#include <cstdint>

// ---------------- problem constants ----------------
#define SEQ   4096
#define HD    64
#define NH    4
#define BM    128          // s rows per CTA
#define BN    64           // t cols per iteration
#define NTH   256
#define ITERS (SEQ/BN)     // 64

// smem strides (floats)
#define SQ 132             // Qs/Ks/Vs row stride (128+4) -> conflict-free frag loads
#define SP 68              // Ps row stride (64+4)

#define QS_OFF 0
#define KS_OFF (BM*SQ)
#define VS_OFF (KS_OFF + BN*SQ)
#define PS_OFF (VS_OFF + BN*SQ)
#define SMEM_FLOATS (PS_OFF + BM*SP)
#define SMEM_BYTES (SMEM_FLOATS*4)   // 169984 bytes

// ---------------- device scratch ----------------
__device__ unsigned g_mask_bits[SEQ * (SEQ / 32)];   // 2 MB packed mask
__device__ float    g_v1sum[NH * HD];                // sum_t V[1,h,t,d]

// ---------------- helpers ----------------
__device__ __forceinline__ float to_tf32(float x) {
    float y; asm("cvt.rna.tf32.f32 %0, %1;" : "=f"(y) : "f"(x)); return y;
}
__device__ __forceinline__ float ex2_fast(float x) {
    float y; asm("ex2.approx.f32 %0, %1;" : "=f"(y) : "f"(x)); return y;
}
__device__ __forceinline__ float rcp_fast(float x) {
    float y; asm("rcp.approx.f32 %0, %1;" : "=f"(y) : "f"(x)); return y;
}
__device__ __forceinline__ float sigp(float d) {
    // p0 = 1/(1+exp(-0.125*d)) ; C = -0.125*log2(e)
    const float C = -0.18033688011111652f;
    return rcp_fast(1.0f + ex2_fast(d * C));
}

#define MMA_TF32(d, a, b) asm volatile( \
    "mma.sync.aligned.m16n8k8.row.col.f32.tf32.tf32.f32 " \
    "{%0,%1,%2,%3}, {%4,%5,%6,%7}, {%8,%9}, {%0,%1,%2,%3};" \
    : "+f"((d)[0]), "+f"((d)[1]), "+f"((d)[2]), "+f"((d)[3]) \
    : "r"(__float_as_uint((a)[0])), "r"(__float_as_uint((a)[1])), \
      "r"(__float_as_uint((a)[2])), "r"(__float_as_uint((a)[3])), \
      "r"(__float_as_uint((b)[0])), "r"(__float_as_uint((b)[1])))

// ---------------- prologue kernels ----------------
__global__ void pack_mask_kernel(const int* __restrict__ mask) {
    int w = blockIdx.x * blockDim.x + threadIdx.x;      // 0 .. SEQ*128-1
    const int4* src = (const int4*)(mask + (size_t)w * 32);
    unsigned bits = 0;
    #pragma unroll
    for (int g = 0; g < 8; g++) {
        int4 v = src[g];
        bits |= (v.x != 0 ? 1u : 0u) << (g * 4 + 0);
        bits |= (v.y != 0 ? 1u : 0u) << (g * 4 + 1);
        bits |= (v.z != 0 ? 1u : 0u) << (g * 4 + 2);
        bits |= (v.w != 0 ? 1u : 0u) << (g * 4 + 3);
    }
    g_mask_bits[w] = bits;
}

__global__ void v1sum_kernel(const float* __restrict__ v) {
    __shared__ float red[256];
    int h = blockIdx.x;
    int d = threadIdx.x & 63;
    int part = threadIdx.x >> 6;
    float s = 0.f;
    for (int t = part; t < SEQ; t += 4)
        s += v[(((size_t)NH + h) * SEQ + t) * HD + d];   // b=1
    red[threadIdx.x] = s;
    __syncthreads();
    if (part == 0)
        g_v1sum[h * HD + d] = red[d] + red[64 + d] + red[128 + d] + red[192 + d];
}

// ---------------- main kernel ----------------
__global__ __launch_bounds__(NTH, 1)
void sdpa_mma_kernel(const float* __restrict__ q,
                     const float* __restrict__ k,
                     const float* __restrict__ v,
                     float* __restrict__ out,
                     float* __restrict__ attn)
{
    extern __shared__ float sm[];
    float* Qs = sm + QS_OFF;   // [128][SQ]  cols 0:64 = q0, 64:128 = q1
    float* Ks = sm + KS_OFF;   // [64][SQ]   cols 0:64 = k0, 64:128 = -k1
    float* Vs = sm + VS_OFF;   // [64][SQ]   cols 0:64 = v0, 64:128 = v1  ([t][n])
    float* Ps = sm + PS_OFF;   // [128][SP]  p0 (tf32)

    const int h   = blockIdx.y;
    const int s0  = blockIdx.x * BM;
    const int tid = threadIdx.x;
    const int w   = tid >> 5;
    const int lane = tid & 31;
    const int gr  = lane >> 2;     // group id (0..7)
    const int ct  = lane & 3;      // thread-in-group
    const int wm  = w & 3;         // warp m-block (32 rows)
    const int wn  = w >> 2;        // warp n-block

    // ---- stage Q (once): [128 rows][128 cols], tf32 ----
    for (int i = tid; i < BM * 32; i += NTH) {
        int row = i >> 5;
        int c4  = i & 31;
        int b   = c4 >> 4;
        int d4  = c4 & 15;
        float4 val = *(const float4*)(q + (((size_t)b * NH + h) * SEQ + s0 + row) * HD + d4 * 4);
        float4 o;
        o.x = to_tf32(val.x); o.y = to_tf32(val.y); o.z = to_tf32(val.z); o.w = to_tf32(val.w);
        *(float4*)(Qs + row * SQ + c4 * 4) = o;
    }

    // ---- persistent O accumulators: warp covers rows wm*32..+32, cols wn*64..+64
    float oc[2][8][4];
    #pragma unroll
    for (int mt = 0; mt < 2; mt++)
        #pragma unroll
        for (int nt = 0; nt < 8; nt++)
            #pragma unroll
            for (int u = 0; u < 4; u++) oc[mt][nt][u] = 0.f;

    for (int it = 0; it < ITERS; ++it) {
        const int t0 = it * BN;
        __syncthreads();   // Ks/Vs/Ps free

        // ---- stage K tile (sign-flipped b=1) and V tile ----
        for (int i = tid; i < BN * 32; i += NTH) {
            int t  = i >> 5;
            int c4 = i & 31;
            int b  = c4 >> 4;
            int d4 = c4 & 15;
            size_t gidx = (((size_t)b * NH + h) * SEQ + t0 + t) * HD + d4 * 4;
            float sgn = b ? -1.f : 1.f;
            float4 kv = *(const float4*)(k + gidx);
            float4 ko;
            ko.x = to_tf32(sgn * kv.x); ko.y = to_tf32(sgn * kv.y);
            ko.z = to_tf32(sgn * kv.z); ko.w = to_tf32(sgn * kv.w);
            *(float4*)(Ks + t * SQ + c4 * 4) = ko;
            float4 vv = *(const float4*)(v + gidx);
            float4 vo;
            vo.x = to_tf32(vv.x); vo.y = to_tf32(vv.y);
            vo.z = to_tf32(vv.z); vo.w = to_tf32(vv.w);
            *(float4*)(Vs + t * SQ + c4 * 4) = vo;
        }
        __syncthreads();

        // ---- MMA1: Delta[128][64] = Qc * Kc^T ; warp tile 32x32 ----
        float sc[2][4][4];
        #pragma unroll
        for (int mt = 0; mt < 2; mt++)
            #pragma unroll
            for (int nt = 0; nt < 4; nt++)
                #pragma unroll
                for (int u = 0; u < 4; u++) sc[mt][nt][u] = 0.f;

        #pragma unroll
        for (int kk = 0; kk < 16; kk++) {
            const int k0 = kk * 8;
            float a[2][4];
            #pragma unroll
            for (int mt = 0; mt < 2; mt++) {
                int r = wm * 32 + mt * 16 + gr;
                a[mt][0] = Qs[r * SQ + k0 + ct];
                a[mt][1] = Qs[(r + 8) * SQ + k0 + ct];
                a[mt][2] = Qs[r * SQ + k0 + ct + 4];
                a[mt][3] = Qs[(r + 8) * SQ + k0 + ct + 4];
            }
            float bfr[4][2];
            #pragma unroll
            for (int nt = 0; nt < 4; nt++) {
                int t = wn * 32 + nt * 8 + gr;
                bfr[nt][0] = Ks[t * SQ + k0 + ct];
                bfr[nt][1] = Ks[t * SQ + k0 + ct + 4];
            }
            #pragma unroll
            for (int mt = 0; mt < 2; mt++)
                #pragma unroll
                for (int nt = 0; nt < 4; nt++)
                    MMA_TF32(sc[mt][nt], a[mt], bfr[nt]);
        }

        // ---- epilogue: sigmoid + mask ; write attn (b0,b1) ; stage P ----
        unsigned mw[4];
        #pragma unroll
        for (int j = 0; j < 4; j++)
            mw[j] = g_mask_bits[(size_t)(s0 + wm * 32 + j * 8 + gr) * 128 + (t0 >> 5) + wn];

        float* attn1 = attn + (size_t)NH * SEQ * SEQ;
        #pragma unroll
        for (int mt = 0; mt < 2; mt++) {
            int r = wm * 32 + mt * 16 + gr;
            unsigned m0 = mw[mt * 2], m1 = mw[mt * 2 + 1];
            #pragma unroll
            for (int nt = 0; nt < 4; nt++) {
                int cl = nt * 8 + ct * 2;          // col within warp's 32
                float* s = sc[mt][nt];
                float p00 = ((m0 >> cl) & 1)       ? 0.5f : sigp(s[0]);
                float p01 = ((m0 >> (cl + 1)) & 1) ? 0.5f : sigp(s[1]);
                float p10 = ((m1 >> cl) & 1)       ? 0.5f : sigp(s[2]);
                float p11 = ((m1 >> (cl + 1)) & 1) ? 0.5f : sigp(s[3]);

                int pc = wn * 32 + cl;
                float2 t0v = make_float2(to_tf32(p00), to_tf32(p01));
                float2 t1v = make_float2(to_tf32(p10), to_tf32(p11));
                *(float2*)(Ps + r * SP + pc)       = t0v;
                *(float2*)(Ps + (r + 8) * SP + pc) = t1v;

                size_t ab = ((size_t)h * SEQ + s0 + r) * SEQ + t0 + pc;
                *(float2*)(attn  + ab)            = make_float2(p00, p01);
                *(float2*)(attn  + ab + 8 * SEQ)  = make_float2(p10, p11);
                *(float2*)(attn1 + ab)            = make_float2(1.f - p00, 1.f - p01);
                *(float2*)(attn1 + ab + 8 * SEQ)  = make_float2(1.f - p10, 1.f - p11);
            }
        }
        __syncthreads();   // Ps visible

        // ---- MMA2: O[128][128] += P0 * [V0|V1] ; warp tile 32x64 ----
        #pragma unroll
        for (int kk = 0; kk < 8; kk++) {
            const int k0 = kk * 8;
            float a[2][4];
            #pragma unroll
            for (int mt = 0; mt < 2; mt++) {
                int r = wm * 32 + mt * 16 + gr;
                a[mt][0] = Ps[r * SP + k0 + ct];
                a[mt][1] = Ps[(r + 8) * SP + k0 + ct];
                a[mt][2] = Ps[r * SP + k0 + ct + 4];
                a[mt][3] = Ps[(r + 8) * SP + k0 + ct + 4];
            }
            float bfr[8][2];
            #pragma unroll
            for (int nt = 0; nt < 8; nt++) {
                int n = wn * 64 + nt * 8 + gr;
                bfr[nt][0] = Vs[(k0 + ct) * SQ + n];
                bfr[nt][1] = Vs[(k0 + ct + 4) * SQ + n];
            }
            #pragma unroll
            for (int mt = 0; mt < 2; mt++)
                #pragma unroll
                for (int nt = 0; nt < 8; nt++)
                    MMA_TF32(oc[mt][nt], a[mt], bfr[nt]);
        }
    }

    // ---- final out write: wn=0 -> b0 = acc ; wn=1 -> b1 = v1sum - acc ----
    const float* vs = g_v1sum + h * HD;
    #pragma unroll
    for (int mt = 0; mt < 2; mt++) {
        int r = s0 + wm * 32 + mt * 16 + gr;
        #pragma unroll
        for (int nt = 0; nt < 8; nt++) {
            int n = wn * 64 + nt * 8 + ct * 2;   // 0..127
            int b = n >> 6;
            int d = n & 63;
            float* c = oc[mt][nt];
            float2 w0, w1;
            if (b == 0) {
                w0 = make_float2(c[0], c[1]);
                w1 = make_float2(c[2], c[3]);
            } else {
                w0 = make_float2(vs[d] - c[0], vs[d + 1] - c[1]);
                w1 = make_float2(vs[d] - c[2], vs[d + 1] - c[3]);
            }
            size_t ob = (((size_t)b * NH + h) * SEQ + r) * HD + d;
            *(float2*)(out + ob)            = w0;
            *(float2*)(out + ob + 8 * HD)   = w1;
        }
    }
}

// ---------------- launcher ----------------
extern "C" void kernel_launch(void* const* d_in, const int* in_sizes, int n_in,
                              void* d_out, int out_size)
{
    const float* q    = (const float*)d_in[0];
    const float* k    = (const float*)d_in[1];
    const float* v    = (const float*)d_in[2];
    const int*   mask = (const int*)  d_in[3];

    float* out  = (float*)d_out;
    float* attn = out + (size_t)2 * NH * SEQ * HD;

    pack_mask_kernel<<<SEQ * 128 / 256, 256>>>(mask);
    v1sum_kernel<<<NH, 256>>>(v);

    cudaFuncSetAttribute(sdpa_mma_kernel,
                         cudaFuncAttributeMaxDynamicSharedMemorySize, SMEM_BYTES);
    dim3 grid(SEQ / BM, NH);
    sdpa_mma_kernel<<<grid, NTH, SMEM_BYTES>>>(q, k, v, out, attn);
}

// round 5
// speedup vs baseline: 1.0024x; 1.0024x over previous
#include <cuda_runtime.h>
#include <cstdint>

// ---------------- problem constants ----------------
#define SEQ   4096
#define HD    64
#define NH    4
#define BM    128          // s rows per CTA
#define BN    64           // t cols per iteration
#define NTH   256
#define ITERS (SEQ/BN)     // 64

// smem strides (floats)
#define SQ 132             // Qs/Ks/Vs row stride (128+4) -> conflict-free frag loads
#define SP 68              // Ps row stride (64+4)

#define QS_OFF 0
#define KS_OFF (BM*SQ)
#define VS_OFF (KS_OFF + BN*SQ)
#define PS_OFF (VS_OFF + BN*SQ)
#define SMEM_FLOATS (PS_OFF + BM*SP)
#define SMEM_BYTES (SMEM_FLOATS*4)   // 169984 bytes

// ---------------- device scratch ----------------
__device__ unsigned g_mask_bits[SEQ * (SEQ / 32)];   // 2 MB packed mask
__device__ float    g_v1sum[NH * HD];                // sum_t V[1,h,t,d]

// ---------------- helpers ----------------
__device__ __forceinline__ float to_tf32(float x) {
    float y; asm("cvt.rna.tf32.f32 %0, %1;" : "=f"(y) : "f"(x)); return y;
}
__device__ __forceinline__ float ex2_fast(float x) {
    float y; asm("ex2.approx.f32 %0, %1;" : "=f"(y) : "f"(x)); return y;
}
__device__ __forceinline__ float rcp_fast(float x) {
    float y; asm("rcp.approx.f32 %0, %1;" : "=f"(y) : "f"(x)); return y;
}
__device__ __forceinline__ float sigp(float d) {
    // p0 = 1/(1+exp(-0.125*d)) ; C = -0.125*log2(e)
    const float C = -0.18033688011111652f;
    return rcp_fast(1.0f + ex2_fast(d * C));
}

#define MMA_TF32(d, a, b) asm volatile( \
    "mma.sync.aligned.m16n8k8.row.col.f32.tf32.tf32.f32 " \
    "{%0,%1,%2,%3}, {%4,%5,%6,%7}, {%8,%9}, {%0,%1,%2,%3};" \
    : "+f"((d)[0]), "+f"((d)[1]), "+f"((d)[2]), "+f"((d)[3]) \
    : "r"(__float_as_uint((a)[0])), "r"(__float_as_uint((a)[1])), \
      "r"(__float_as_uint((a)[2])), "r"(__float_as_uint((a)[3])), \
      "r"(__float_as_uint((b)[0])), "r"(__float_as_uint((b)[1])))

// ---------------- prologue kernels ----------------
__global__ void pack_mask_kernel(const int* __restrict__ mask) {
    int w = blockIdx.x * blockDim.x + threadIdx.x;      // 0 .. SEQ*128-1
    const int4* src = (const int4*)(mask + (size_t)w * 32);
    unsigned bits = 0;
    #pragma unroll
    for (int g = 0; g < 8; g++) {
        int4 v = src[g];
        bits |= (v.x != 0 ? 1u : 0u) << (g * 4 + 0);
        bits |= (v.y != 0 ? 1u : 0u) << (g * 4 + 1);
        bits |= (v.z != 0 ? 1u : 0u) << (g * 4 + 2);
        bits |= (v.w != 0 ? 1u : 0u) << (g * 4 + 3);
    }
    g_mask_bits[w] = bits;
}

__global__ void v1sum_kernel(const float* __restrict__ v) {
    __shared__ float red[256];
    int h = blockIdx.x;
    int d = threadIdx.x & 63;
    int part = threadIdx.x >> 6;
    float s = 0.f;
    for (int t = part; t < SEQ; t += 4)
        s += v[(((size_t)NH + h) * SEQ + t) * HD + d];   // b=1
    red[threadIdx.x] = s;
    __syncthreads();
    if (part == 0)
        g_v1sum[h * HD + d] = red[d] + red[64 + d] + red[128 + d] + red[192 + d];
}

// ---------------- main kernel ----------------
__global__ __launch_bounds__(NTH, 1)
void sdpa_mma_kernel(const float* __restrict__ q,
                     const float* __restrict__ k,
                     const float* __restrict__ v,
                     float* __restrict__ out,
                     float* __restrict__ attn)
{
    extern __shared__ float sm[];
    float* Qs = sm + QS_OFF;   // [128][SQ]  cols 0:64 = q0, 64:128 = q1
    float* Ks = sm + KS_OFF;   // [64][SQ]   cols 0:64 = k0, 64:128 = -k1
    float* Vs = sm + VS_OFF;   // [64][SQ]   cols 0:64 = v0, 64:128 = v1  ([t][n])
    float* Ps = sm + PS_OFF;   // [128][SP]  p0 (tf32)

    const int h   = blockIdx.y;
    const int s0  = blockIdx.x * BM;
    const int tid = threadIdx.x;
    const int w   = tid >> 5;
    const int lane = tid & 31;
    const int gr  = lane >> 2;     // group id (0..7)
    const int ct  = lane & 3;      // thread-in-group
    const int wm  = w & 3;         // warp m-block (32 rows)
    const int wn  = w >> 2;        // warp n-block

    // ---- stage Q (once): [128 rows][128 cols], tf32 ----
    for (int i = tid; i < BM * 32; i += NTH) {
        int row = i >> 5;
        int c4  = i & 31;
        int b   = c4 >> 4;
        int d4  = c4 & 15;
        float4 val = *(const float4*)(q + (((size_t)b * NH + h) * SEQ + s0 + row) * HD + d4 * 4);
        float4 o;
        o.x = to_tf32(val.x); o.y = to_tf32(val.y); o.z = to_tf32(val.z); o.w = to_tf32(val.w);
        *(float4*)(Qs + row * SQ + c4 * 4) = o;
    }

    // ---- persistent O accumulators: warp covers rows wm*32..+32, cols wn*64..+64
    float oc[2][8][4];
    #pragma unroll
    for (int mt = 0; mt < 2; mt++)
        #pragma unroll
        for (int nt = 0; nt < 8; nt++)
            #pragma unroll
            for (int u = 0; u < 4; u++) oc[mt][nt][u] = 0.f;

    for (int it = 0; it < ITERS; ++it) {
        const int t0 = it * BN;
        __syncthreads();   // Ks/Vs/Ps free

        // ---- stage K tile (sign-flipped b=1) and V tile ----
        for (int i = tid; i < BN * 32; i += NTH) {
            int t  = i >> 5;
            int c4 = i & 31;
            int b  = c4 >> 4;
            int d4 = c4 & 15;
            size_t gidx = (((size_t)b * NH + h) * SEQ + t0 + t) * HD + d4 * 4;
            float sgn = b ? -1.f : 1.f;
            float4 kv = *(const float4*)(k + gidx);
            float4 ko;
            ko.x = to_tf32(sgn * kv.x); ko.y = to_tf32(sgn * kv.y);
            ko.z = to_tf32(sgn * kv.z); ko.w = to_tf32(sgn * kv.w);
            *(float4*)(Ks + t * SQ + c4 * 4) = ko;
            float4 vv = *(const float4*)(v + gidx);
            float4 vo;
            vo.x = to_tf32(vv.x); vo.y = to_tf32(vv.y);
            vo.z = to_tf32(vv.z); vo.w = to_tf32(vv.w);
            *(float4*)(Vs + t * SQ + c4 * 4) = vo;
        }
        __syncthreads();

        // ---- MMA1: Delta[128][64] = Qc * Kc^T ; warp tile 32x32 ----
        float sc[2][4][4];
        #pragma unroll
        for (int mt = 0; mt < 2; mt++)
            #pragma unroll
            for (int nt = 0; nt < 4; nt++)
                #pragma unroll
                for (int u = 0; u < 4; u++) sc[mt][nt][u] = 0.f;

        #pragma unroll
        for (int kk = 0; kk < 16; kk++) {
            const int k0 = kk * 8;
            float a[2][4];
            #pragma unroll
            for (int mt = 0; mt < 2; mt++) {
                int r = wm * 32 + mt * 16 + gr;
                a[mt][0] = Qs[r * SQ + k0 + ct];
                a[mt][1] = Qs[(r + 8) * SQ + k0 + ct];
                a[mt][2] = Qs[r * SQ + k0 + ct + 4];
                a[mt][3] = Qs[(r + 8) * SQ + k0 + ct + 4];
            }
            float bfr[4][2];
            #pragma unroll
            for (int nt = 0; nt < 4; nt++) {
                int t = wn * 32 + nt * 8 + gr;
                bfr[nt][0] = Ks[t * SQ + k0 + ct];
                bfr[nt][1] = Ks[t * SQ + k0 + ct + 4];
            }
            #pragma unroll
            for (int mt = 0; mt < 2; mt++)
                #pragma unroll
                for (int nt = 0; nt < 4; nt++)
                    MMA_TF32(sc[mt][nt], a[mt], bfr[nt]);
        }

        // ---- epilogue: sigmoid + mask ; write attn (b0,b1) ; stage P ----
        unsigned mw[4];
        #pragma unroll
        for (int j = 0; j < 4; j++)
            mw[j] = g_mask_bits[(size_t)(s0 + wm * 32 + j * 8 + gr) * 128 + (t0 >> 5) + wn];

        float* attn1 = attn + (size_t)NH * SEQ * SEQ;
        #pragma unroll
        for (int mt = 0; mt < 2; mt++) {
            int r = wm * 32 + mt * 16 + gr;
            unsigned m0 = mw[mt * 2], m1 = mw[mt * 2 + 1];
            #pragma unroll
            for (int nt = 0; nt < 4; nt++) {
                int cl = nt * 8 + ct * 2;          // col within warp's 32
                float* s = sc[mt][nt];
                float p00 = ((m0 >> cl) & 1)       ? 0.5f : sigp(s[0]);
                float p01 = ((m0 >> (cl + 1)) & 1) ? 0.5f : sigp(s[1]);
                float p10 = ((m1 >> cl) & 1)       ? 0.5f : sigp(s[2]);
                float p11 = ((m1 >> (cl + 1)) & 1) ? 0.5f : sigp(s[3]);

                int pc = wn * 32 + cl;
                float2 t0v = make_float2(to_tf32(p00), to_tf32(p01));
                float2 t1v = make_float2(to_tf32(p10), to_tf32(p11));
                *(float2*)(Ps + r * SP + pc)       = t0v;
                *(float2*)(Ps + (r + 8) * SP + pc) = t1v;

                size_t ab = ((size_t)h * SEQ + s0 + r) * SEQ + t0 + pc;
                *(float2*)(attn  + ab)            = make_float2(p00, p01);
                *(float2*)(attn  + ab + 8 * SEQ)  = make_float2(p10, p11);
                *(float2*)(attn1 + ab)            = make_float2(1.f - p00, 1.f - p01);
                *(float2*)(attn1 + ab + 8 * SEQ)  = make_float2(1.f - p10, 1.f - p11);
            }
        }
        __syncthreads();   // Ps visible

        // ---- MMA2: O[128][128] += P0 * [V0|V1] ; warp tile 32x64 ----
        #pragma unroll
        for (int kk = 0; kk < 8; kk++) {
            const int k0 = kk * 8;
            float a[2][4];
            #pragma unroll
            for (int mt = 0; mt < 2; mt++) {
                int r = wm * 32 + mt * 16 + gr;
                a[mt][0] = Ps[r * SP + k0 + ct];
                a[mt][1] = Ps[(r + 8) * SP + k0 + ct];
                a[mt][2] = Ps[r * SP + k0 + ct + 4];
                a[mt][3] = Ps[(r + 8) * SP + k0 + ct + 4];
            }
            float bfr[8][2];
            #pragma unroll
            for (int nt = 0; nt < 8; nt++) {
                int n = wn * 64 + nt * 8 + gr;
                bfr[nt][0] = Vs[(k0 + ct) * SQ + n];
                bfr[nt][1] = Vs[(k0 + ct + 4) * SQ + n];
            }
            #pragma unroll
            for (int mt = 0; mt < 2; mt++)
                #pragma unroll
                for (int nt = 0; nt < 8; nt++)
                    MMA_TF32(oc[mt][nt], a[mt], bfr[nt]);
        }
    }

    // ---- final out write: wn=0 -> b0 = acc ; wn=1 -> b1 = v1sum - acc ----
    const float* vs = g_v1sum + h * HD;
    #pragma unroll
    for (int mt = 0; mt < 2; mt++) {
        int r = s0 + wm * 32 + mt * 16 + gr;
        #pragma unroll
        for (int nt = 0; nt < 8; nt++) {
            int n = wn * 64 + nt * 8 + ct * 2;   // 0..127
            int b = n >> 6;
            int d = n & 63;
            float* c = oc[mt][nt];
            float2 w0, w1;
            if (b == 0) {
                w0 = make_float2(c[0], c[1]);
                w1 = make_float2(c[2], c[3]);
            } else {
                w0 = make_float2(vs[d] - c[0], vs[d + 1] - c[1]);
                w1 = make_float2(vs[d] - c[2], vs[d + 1] - c[3]);
            }
            size_t ob = (((size_t)b * NH + h) * SEQ + r) * HD + d;
            *(float2*)(out + ob)            = w0;
            *(float2*)(out + ob + 8 * HD)   = w1;
        }
    }
}

// ---------------- launcher ----------------
extern "C" void kernel_launch(void* const* d_in, const int* in_sizes, int n_in,
                              void* d_out, int out_size)
{
    const float* q    = (const float*)d_in[0];
    const float* k    = (const float*)d_in[1];
    const float* v    = (const float*)d_in[2];
    const int*   mask = (const int*)  d_in[3];

    float* out  = (float*)d_out;
    float* attn = out + (size_t)2 * NH * SEQ * HD;

    pack_mask_kernel<<<SEQ * 128 / 256, 256>>>(mask);
    v1sum_kernel<<<NH, 256>>>(v);

    cudaFuncSetAttribute(sdpa_mma_kernel,
                         cudaFuncAttributeMaxDynamicSharedMemorySize, SMEM_BYTES);
    dim3 grid(SEQ / BM, NH);
    sdpa_mma_kernel<<<grid, NTH, SMEM_BYTES>>>(q, k, v, out, attn);
}